// round 13
// baseline (speedup 1.0000x reference)
#include <cuda_runtime.h>

typedef unsigned long long ULL;

// ---------------- device scratch (no allocations allowed) ----------------
// Packed, zero-padded weights: wpad_g[lp][c] = (W_in_real[c][lp-9], W_in_imag[c][lp-9]),
// zero outside l in [0, 4086]. lp in [0, 4105).
__device__ __align__(16) float2 wpad_g[4105 * 16];
// Stage-1 partial sums: [b][s][idx]  (b:256, s:8, idx:320) = 2.6MB, L2-resident
__device__ float fpart_g[256 * 8 * 320];
// Pre-batchnorm output: [b][c*2+o]
__device__ float out_g[256 * 32];

// ---------------- packed f32x2 FMA (FFMA2) ----------------
__device__ __forceinline__ ULL fma2(ULL a, ULL b, ULL c) {
    ULL d;
    asm("fma.rn.f32x2 %0, %1, %2, %3;" : "=l"(d) : "l"(a), "l"(b), "l"(c));
    return d;
}
__device__ __forceinline__ float2 u2f2(ULL v) {
    return make_float2(__uint_as_float((unsigned)(v & 0xffffffffULL)),
                       __uint_as_float((unsigned)(v >> 32)));
}

// ---------------- kernel 0: pack + pad weights ----------------
__global__ void __launch_bounds__(1024) pack_kernel(const float* __restrict__ wr,
                                                    const float* __restrict__ wi) {
    int idx = blockIdx.x * blockDim.x + threadIdx.x;
    if (idx >= 4105 * 16) return;
    int lp = idx >> 4;
    int c  = idx & 15;
    int l  = lp - 9;
    float2 v = make_float2(0.f, 0.f);
    if (l >= 0 && l < 4087) {
        v.x = wr[c * 4087 + l];
        v.y = wi[c * 4087 + l];
    }
    wpad_g[lp * 16 + c] = v;
}

// ---------------- kernel 1: depthwise sliding filters (stage 1) ----------------
// R2-shape: grid (256 batches, 8 segments) = 2048 blocks, 256 threads
// = 16 channels x 16 j-chunks, 32 positions/thread. Weights LDG'd per
// position from L2-resident wpad_g into a 10-deep rotating register window
// (low registers -> ~5 blocks/SM -> ~40 resident warps: latency hidden by
// warp count, not per-thread MLP). Epilogue: shfl j-pair combine + 8-row
// conflict-free smem reduce.
// f[b,w,c] = sum_p x[b,p,c] * Wpad[p + 9 - w]
__global__ void __launch_bounds__(256) stage1_kernel(const float* __restrict__ x) {
    __shared__ float red[8][320];      // 10.2KB per-warp partials

    int b    = blockIdx.x;
    int s    = blockIdx.y;             // 0..7
    int tid  = threadIdx.x;
    int c    = tid & 15;
    int j    = tid >> 4;               // 0..15
    int ps   = s * 512 + j * 32;
    int warp = tid >> 5;               // 0..7

    const ULL* xp = (const ULL*)x + ((size_t)b * 4096 + ps) * 16 + c;
    const ULL* wp = (const ULL*)wpad_g + (size_t)ps * 16 + c;   // wp[k*16] = Wpad[ps+k]

    // rotating window: slot m%10 holds Wpad[ps+m]; preload m = 0..8
    ULL wbuf[10];
#pragma unroll
    for (int k = 0; k < 9; k++) wbuf[k] = wp[(size_t)k * 16];

    ULL acc[10];
#pragma unroll
    for (int w = 0; w < 10; w++) acc[w] = 0ULL;

#pragma unroll
    for (int t = 0; t < 32; t++) {
        ULL xv = xp[(size_t)t * 16];
        wbuf[(t + 9) % 10] = wp[(size_t)(t + 9) * 16];   // Wpad[ps+t+9]
#pragma unroll
        for (int w = 0; w < 10; w++)
            acc[w] = fma2(xv, wbuf[(t + 9 - w) % 10], acc[w]);   // Wpad[p+9-w]
    }

    // combine j-pair within warp (lane L with L^16); lanes 0-15 store
#pragma unroll
    for (int w = 0; w < 10; w++) {
        float2 f = u2f2(acc[w]);
        f.x += __shfl_xor_sync(0xffffffffu, f.x, 16);
        f.y += __shfl_xor_sync(0xffffffffu, f.y, 16);
        if ((tid & 16) == 0) {
            red[warp][(c * 10 + w) * 2 + 0] = f.x;
            red[warp][(c * 10 + w) * 2 + 1] = f.y;
        }
    }
    __syncthreads();

    // reduce 8 warp-rows over 320 entries (stride 320 ≡ 0 mod 32: conflict-free)
    for (int idx = tid; idx < 320; idx += 256) {
        float v = 0.f;
#pragma unroll
        for (int ww = 0; ww < 8; ww++) v += red[ww][idx];
        fpart_g[((size_t)b * 8 + s) * 320 + idx] = v;
    }
}

// ---------------- kernel 2: amp + Linear(2C->2) + out filter ----------------
// one block per b, 320 threads; fpart is L2-hot, read directly (coalesced).
__global__ void __launch_bounds__(320) stage23_kernel(const float* __restrict__ Wnl,
                                                      const float* __restrict__ WoR,
                                                      const float* __restrict__ WoI) {
    __shared__ float tf[10][32];       // [w][i], i<16: amp*fr, i>=16: amp*fi
    __shared__ float contrib[10][32];  // [w][c*2+o]

    int b = blockIdx.x;
    int tid = threadIdx.x;

    // reduce over s=8 directly from L2; idx = (c*10+w)*2+o = tid (coalesced)
    {
        const float* fp = fpart_g + (size_t)b * 8 * 320 + tid;
        float v = 0.f;
#pragma unroll
        for (int s = 0; s < 8; s++) v += fp[s * 320];
        float other = __shfl_xor_sync(0xffffffffu, v, 1);
        float amp = v * v + other * other;
        int pair = tid >> 1;          // c*10 + w
        int o    = tid & 1;
        int cc   = pair / 10;
        int w    = pair - cc * 10;
        tf[w][cc + 16 * o] = amp * v; // o=0: amp*fr ; o=1: amp*fi
    }
    __syncthreads();

    // per-channel Linear(2C->2) + output-filter weighting
    {
        int w = tid >> 5;
        int q = tid & 31;
        int cc = q >> 1;
        int o  = q & 1;
        float acc = 0.f;
        const float* wn = Wnl + (cc * 2 + o) * 32;
#pragma unroll
        for (int i = 0; i < 32; i++) acc += tf[w][i] * wn[i];
        float wo = (o == 0 ? WoR : WoI)[cc * 10 + w];
        contrib[w][q] = acc * wo;
    }
    __syncthreads();

    // sum over w, write pre-BN output
    if (tid < 32) {
        float ssum = 0.f;
#pragma unroll
        for (int ww = 0; ww < 10; ww++) ssum += contrib[ww][tid];
        out_g[b * 32 + tid] = ssum;
    }
}

// ---------------- kernel 3: BatchNorm1d (training stats), 1 block ----------------
__global__ void __launch_bounds__(512) bn_kernel(const float* __restrict__ gamma,
                                                 const float* __restrict__ beta,
                                                 float* __restrict__ out) {
    __shared__ float bnbuf[32][257];   // [q = ch*2+o][b], padded rows

    int tid = threadIdx.x;
#pragma unroll
    for (int k = 0; k < 16; k++) {
        int i = tid + k * 512;
        bnbuf[i & 31][i >> 5] = out_g[i];
    }
    __syncthreads();

    // one warp per channel
    int ch = tid >> 5, lane = tid & 31;
    float s1 = 0.f;
#pragma unroll
    for (int j = 0; j < 8; j++) {
        int bb = lane + j * 32;
        s1 += bnbuf[2 * ch][bb] + bnbuf[2 * ch + 1][bb];
    }
#pragma unroll
    for (int off = 16; off; off >>= 1) s1 += __shfl_xor_sync(0xffffffffu, s1, off);
    float mean = s1 * (1.f / 512.f);

    float s2 = 0.f;
#pragma unroll
    for (int j = 0; j < 8; j++) {
        int bb = lane + j * 32;
        float d0 = bnbuf[2 * ch][bb] - mean;
        float d1 = bnbuf[2 * ch + 1][bb] - mean;
        s2 += d0 * d0 + d1 * d1;
    }
#pragma unroll
    for (int off = 16; off; off >>= 1) s2 += __shfl_xor_sync(0xffffffffu, s2, off);
    float inv = rsqrtf(s2 * (1.f / 512.f) + 1e-5f);

    float g = gamma[ch], bb_ = beta[ch];
#pragma unroll
    for (int j = 0; j < 8; j++) {
        int bb = lane + j * 32;
        out[bb * 32 + 2 * ch]     = (bnbuf[2 * ch][bb] - mean) * inv * g + bb_;
        out[bb * 32 + 2 * ch + 1] = (bnbuf[2 * ch + 1][bb] - mean) * inv * g + bb_;
    }
}

// ---------------- launch ----------------
extern "C" void kernel_launch(void* const* d_in, const int* in_sizes, int n_in,
                              void* d_out, int out_size) {
    const float* x     = (const float*)d_in[0];
    const float* wir   = (const float*)d_in[1];
    const float* wii   = (const float*)d_in[2];
    const float* wnl   = (const float*)d_in[3];
    const float* wor   = (const float*)d_in[4];
    const float* woi   = (const float*)d_in[5];
    const float* gamma = (const float*)d_in[6];
    const float* beta  = (const float*)d_in[7];
    float* out = (float*)d_out;

    pack_kernel<<<(4105 * 16 + 1023) / 1024, 1024>>>(wir, wii);
    stage1_kernel<<<dim3(256, 8), 256>>>(x);
    stage23_kernel<<<256, 320>>>(wnl, wor, woi);
    bn_kernel<<<1, 512>>>(gamma, beta, out);
}

// round 14
// speedup vs baseline: 1.6604x; 1.6604x over previous
#include <cuda_runtime.h>

typedef unsigned long long ULL;

// ---------------- device scratch (no allocations allowed) ----------------
// Packed, zero-padded weights: Wpad[lp][c] = (Win_real[c][lp-9], Win_imag[c][lp-9]),
// zero outside l in [0, 4086]. lp in [0, 4105).
__device__ __align__(16) float2 wpad_g[4105 * 16];
// Stage-1 partial sums: [b][s][idx]  (b:256, s:8, idx:320 = (c*10+w)*2+comp)
__device__ float fpart_g[256 * 8 * 320];
// Pre-batchnorm output: [b][c*2+o]
__device__ float out_g[256 * 32];

// ---------------- packed f32x2 FMA (FFMA2) ----------------
__device__ __forceinline__ ULL fma2(ULL a, ULL b, ULL c) {
    ULL d;
    asm("fma.rn.f32x2 %0, %1, %2, %3;" : "=l"(d) : "l"(a), "l"(b), "l"(c));
    return d;
}

// ---------------- kernel 0: pack + pad weights (R2 verbatim) ----------------
__global__ void pack_kernel(const float* __restrict__ wr, const float* __restrict__ wi) {
    int idx = blockIdx.x * blockDim.x + threadIdx.x;
    if (idx >= 4105 * 16) return;
    int lp = idx >> 4;
    int c  = idx & 15;
    int l  = lp - 9;
    float2 v = make_float2(0.f, 0.f);
    if (l >= 0 && l < 4087) {
        v.x = wr[c * 4087 + l];
        v.y = wi[c * 4087 + l];
    }
    wpad_g[lp * 16 + c] = v;
}

// ---------------- kernel 1: depthwise sliding filters (R2 verbatim) ----------------
// grid (256, 8), block 256 = 16 channels x 16 n-chunks; each thread does 32
// contiguous positions with a rotating 10-deep register weight window.
__global__ void __launch_bounds__(256) stage1_kernel(const float* __restrict__ x) {
    __shared__ float red[16][322];   // [j][(c*10+w)*2+comp], padded row

    int b = blockIdx.x;
    int s = blockIdx.y;
    int tid = threadIdx.x;
    int c = tid & 15;
    int j = tid >> 4;
    int ps = s * 512 + j * 32;       // starting position p for this thread

    const ULL* xp = (const ULL*)x + ((size_t)b * 4096 + (size_t)ps) * 16 + c;
    const ULL* wp = (const ULL*)wpad_g + (size_t)ps * 16 + c;

    // slot m holds Wt[l] with l == m-9 (mod 10); init window Wt[ps .. ps+8]
    ULL wbuf[10];
#pragma unroll
    for (int k = 0; k < 9; k++) wbuf[k] = wp[(size_t)k * 16];

    ULL acc[10];
#pragma unroll
    for (int w = 0; w < 10; w++) acc[w] = 0ULL;

#pragma unroll
    for (int t = 0; t < 32; t++) {
        ULL xv = xp[(size_t)t * 16];
        wbuf[(t + 9) % 10] = wp[(size_t)(t + 9) * 16];   // Wpad[ps+t+9]
#pragma unroll
        for (int w = 0; w < 10; w++)
            acc[w] = fma2(xv, wbuf[(t + 9 - w) % 10], acc[w]);  // Wpad[p-w+9]
    }

    // dump to smem: red[j][(c*10+w)*2 + comp]
#pragma unroll
    for (int w = 0; w < 10; w++) {
        red[j][(c * 10 + w) * 2 + 0] = __uint_as_float((unsigned)(acc[w] & 0xffffffffULL));
        red[j][(c * 10 + w) * 2 + 1] = __uint_as_float((unsigned)(acc[w] >> 32));
    }
    __syncthreads();

    // reduce the 16 n-chunks over all 320 entries with 256 threads
    for (int idx = tid; idx < 320; idx += 256) {
        float v = 0.f;
#pragma unroll
        for (int jj = 0; jj < 16; jj++) v += red[jj][idx];
        fpart_g[((size_t)(b * 8 + s)) * 320 + idx] = v;
    }
}

// ---------------- kernel 2: amp + Linear(2C->2) + out filter (THE ONE CHANGE) ----------------
// one block per b, 320 threads; coalesced s-reduction directly from L2-hot fpart.
__global__ void __launch_bounds__(320) stage23_kernel(const float* __restrict__ Wnl,
                                                      const float* __restrict__ WoR,
                                                      const float* __restrict__ WoI) {
    __shared__ float tf[10][32];       // [w][i], i<16: amp*fr, i>=16: amp*fi
    __shared__ float contrib[10][32];  // [w][c*2+o]

    int b = blockIdx.x;
    int tid = threadIdx.x;

    // reduce over s=8 directly from L2; idx = (c*10+w)*2+o = tid (coalesced)
    {
        const float* fp = fpart_g + (size_t)b * 8 * 320 + tid;
        float v = 0.f;
#pragma unroll
        for (int s = 0; s < 8; s++) v += fp[s * 320];
        float other = __shfl_xor_sync(0xffffffffu, v, 1);
        float amp = v * v + other * other;
        int pair = tid >> 1;          // c*10 + w
        int o    = tid & 1;
        int cc   = pair / 10;
        int w    = pair - cc * 10;
        tf[w][cc + 16 * o] = amp * v; // o=0: amp*fr ; o=1: amp*fi
    }
    __syncthreads();

    // per-channel Linear(2C->2) + output-filter weighting
    {
        int w = tid >> 5;
        int q = tid & 31;
        int cc = q >> 1;
        int o  = q & 1;
        float acc = 0.f;
        const float* wn = Wnl + (cc * 2 + o) * 32;
#pragma unroll
        for (int i = 0; i < 32; i++) acc += tf[w][i] * wn[i];
        float wo = (o == 0 ? WoR : WoI)[cc * 10 + w];
        contrib[w][q] = acc * wo;
    }
    __syncthreads();

    // sum over w, write pre-BN output
    if (tid < 32) {
        float ssum = 0.f;
#pragma unroll
        for (int ww = 0; ww < 10; ww++) ssum += contrib[ww][tid];
        out_g[b * 32 + tid] = ssum;
    }
}

// ---------------- kernel 3: BatchNorm1d (R2 verbatim: 16 blocks x 512) ----------------
__global__ void __launch_bounds__(512) bn_kernel(const float* __restrict__ gamma,
                                                 const float* __restrict__ beta,
                                                 float* __restrict__ out) {
    __shared__ float sbuf[16];
    __shared__ float stat;

    int c = blockIdx.x;
    int t = threadIdx.x;
    int b = t >> 1;
    int o = t & 1;

    float v = out_g[b * 32 + c * 2 + o];

    // pass 1: mean
    float r = v;
#pragma unroll
    for (int off = 16; off; off >>= 1) r += __shfl_xor_sync(0xffffffffu, r, off);
    if ((t & 31) == 0) sbuf[t >> 5] = r;
    __syncthreads();
    if (t < 32) {
        float z = (t < 16) ? sbuf[t] : 0.f;
#pragma unroll
        for (int off = 8; off; off >>= 1) z += __shfl_xor_sync(0xffffffffu, z, off);
        if (t == 0) stat = z * (1.f / 512.f);
    }
    __syncthreads();
    float mean = stat;
    float d = v - mean;

    // pass 2: variance of centered values
    r = d * d;
#pragma unroll
    for (int off = 16; off; off >>= 1) r += __shfl_xor_sync(0xffffffffu, r, off);
    if ((t & 31) == 0) sbuf[t >> 5] = r;
    __syncthreads();
    if (t < 32) {
        float z = (t < 16) ? sbuf[t] : 0.f;
#pragma unroll
        for (int off = 8; off; off >>= 1) z += __shfl_xor_sync(0xffffffffu, z, off);
        if (t == 0) stat = rsqrtf(z * (1.f / 512.f) + 1e-5f);
    }
    __syncthreads();

    out[b * 32 + c * 2 + o] = d * stat * gamma[c] + beta[c];
}

// ---------------- launch ----------------
extern "C" void kernel_launch(void* const* d_in, const int* in_sizes, int n_in,
                              void* d_out, int out_size) {
    const float* x     = (const float*)d_in[0];
    const float* wir   = (const float*)d_in[1];
    const float* wii   = (const float*)d_in[2];
    const float* wnl   = (const float*)d_in[3];
    const float* wor   = (const float*)d_in[4];
    const float* woi   = (const float*)d_in[5];
    const float* gamma = (const float*)d_in[6];
    const float* beta  = (const float*)d_in[7];
    float* out = (float*)d_out;

    pack_kernel<<<(4105 * 16 + 255) / 256, 256>>>(wir, wii);
    stage1_kernel<<<dim3(256, 8), 256>>>(x);
    stage23_kernel<<<256, 320>>>(wnl, wor, woi);
    bn_kernel<<<16, 512>>>(gamma, beta, out);
}